// round 16
// baseline (speedup 1.0000x reference)
#include <cuda_runtime.h>
#include <math.h>
#include <cstdint>

#define BATCH 4
#define SEQ   4096
#define EMB   1024
#define HDIM  128
#define FULLM 0xffffffffu

// ---------------------------------------------------------------------------
// scratch (allocation-free: __device__ globals) — all tf32-rounded fp32
// ---------------------------------------------------------------------------
// Q, K: [b*SEQ+row][dim], dims pair-permuted within 8-groups ((c,c+4) adjacent)
__device__ float g_Q[(size_t)BATCH * SEQ * HDIM];
__device__ float g_K[(size_t)BATCH * SEQ * HDIM];
// V transposed: [b][dim][seq], keys pair-permuted within 8-groups
__device__ float g_Vt[(size_t)BATCH * HDIM * SEQ];
// W: [which][n][k], k pair-permuted; which: 0=K,1=Q,2=V
__device__ float g_Wp[3 * HDIM * EMB];
// split-K attention partials (numerator O, running max m, running sum l)
__device__ float g_O0[(size_t)BATCH * SEQ * HDIM];
__device__ float g_O1[(size_t)BATCH * SEQ * HDIM];
__device__ float g_Mp[2][BATCH * SEQ];
__device__ float g_Lp[2][BATCH * SEQ];

// ===========================================================================
// helpers
// ===========================================================================
__device__ __forceinline__ int perm8(int i) { return (i < 4) ? 2 * i : 2 * (i - 4) + 1; }

__device__ __forceinline__ float totf32(float x) {
    uint32_t r;
    asm("cvt.rna.tf32.f32 %0, %1;" : "=r"(r) : "f"(x));
    return __uint_as_float(r);
}

__device__ __forceinline__ void mma_tf32(float& c0, float& c1, float& c2, float& c3,
    float a0, float a1, float a2, float a3, float b0, float b1) {
    asm volatile(
        "mma.sync.aligned.m16n8k8.row.col.f32.tf32.tf32.f32 "
        "{%0,%1,%2,%3}, {%4,%5,%6,%7}, {%8,%9}, {%0,%1,%2,%3};"
        : "+f"(c0), "+f"(c1), "+f"(c2), "+f"(c3)
        : "r"(__float_as_uint(a0)), "r"(__float_as_uint(a1)),
          "r"(__float_as_uint(a2)), "r"(__float_as_uint(a3)),
          "r"(__float_as_uint(b0)), "r"(__float_as_uint(b1)));
}

#define CP_ASYNC16(dst, src) \
    asm volatile("cp.async.cg.shared.global [%0], [%1], 16;" :: "r"(dst), "l"(src))
#define CP_COMMIT()  asm volatile("cp.async.commit_group;" ::: "memory")
#define CP_WAIT0()   asm volatile("cp.async.wait_group 0;" ::: "memory")
#define CP_WAIT1()   asm volatile("cp.async.wait_group 1;" ::: "memory")

__device__ __forceinline__ uint32_t smem_to_u32(const void* p) {
    uint32_t a;
    asm("{ .reg .u64 t; cvta.to.shared.u64 t, %1; cvt.u32.u64 %0, t; }"
        : "=r"(a) : "l"(p));
    return a;
}

__device__ __forceinline__ float ex2(float x) {
    float y;
    asm("ex2.approx.f32 %0, %1;" : "=f"(y) : "f"(x));
    return y;
}

// ===========================================================================
// prep: W -> tf32-rounded, k pair-permuted  (x prep is fused into proj)
// ===========================================================================
__global__ __launch_bounds__(256) void wprep_kernel(
    const float* __restrict__ Wk,
    const float* __restrict__ Wq,
    const float* __restrict__ Wv)
{
    int idx = blockIdx.x * 256 + threadIdx.x;
    if (idx >= 3 * HDIM * EMB) return;
    int which = idx >> 17;
    int within = idx & ((HDIM * EMB) - 1);
    int k = within & (EMB - 1);
    int n = within >> 10;
    const float* W = (which == 0) ? Wk : (which == 1) ? Wq : Wv;
    g_Wp[which * HDIM * EMB + n * EMB + (k & ~7) + perm8(k & 7)] = totf32(W[within]);
}

// ===========================================================================
// Projection GEMM, tf32, software-pipelined:
//   W double-buffered via cp.async (prefetched one chunk ahead),
//   x register-prefetched one chunk ahead (converted in regs -> smem).
// 2D warp tiling: 8 warps = 4(M) x 2(N); each warp 32 rows x 64 cols.
// grid (128 m-tiles, 3 heads), 256 threads, 2 CTAs/SM (110592 B, <=128 regs).
// ===========================================================================
#define PJ_RS   288
#define PJ_X    0
#define PJ_W0   36864
#define PJ_W1   73728
#define PJ_SMEM 110592

extern __shared__ char dsmem[];

__device__ __forceinline__ void proj_w_prefetch(uint32_t dst_buf, int which, int e0, int tid)
{
    // FULL 128x64 float tile = 2048 uint4 -> j < 8  (R14 bug: j < 4 loaded half)
#pragma unroll
    for (int j = 0; j < 8; j++) {
        int idx = tid + j * 256;
        int row = idx >> 4, c16 = idx & 15;
        CP_ASYNC16(dst_buf + (uint32_t)row * PJ_RS + c16 * 16,
                   (const void*)(g_Wp + (size_t)(which * HDIM + row) * EMB + e0 + c16 * 4));
    }
    CP_COMMIT();
}

__global__ __launch_bounds__(256, 2) void proj_mma_kernel(const float* __restrict__ x)
{
    char* smem = dsmem;
    uint32_t sb = smem_to_u32(smem);
    const int tid  = threadIdx.x;
    const int lane = tid & 31;
    const int w    = tid >> 5;
    const int wm   = w & 3;        // M group: rows [wm*32, +32)
    const int wn   = w >> 2;       // N group: cols [wn*64, +64)
    const int m0   = blockIdx.x * 128;
    const int which = blockIdx.y;

    float o[2][8][4];
#pragma unroll
    for (int mt = 0; mt < 2; mt++)
#pragma unroll
        for (int nt = 0; nt < 8; nt++)
#pragma unroll
            for (int k = 0; k < 4; k++) o[mt][nt][k] = 0.0f;

    const uint32_t a_row0 = (uint32_t)(wm * 32 + (lane >> 2)) * PJ_RS + (lane & 3) * 8;
    const uint32_t b_base = (uint32_t)(wn * 64 + (lane >> 2)) * PJ_RS + (lane & 3) * 8;

    // x load mapping: idx = tid + j*256 -> row = row0 + 32j, c8 fixed
    const int xrow0 = tid >> 3;
    const int xc8   = tid & 7;
    const float* xbase = x + (size_t)(m0 + xrow0) * EMB + xc8 * 8;

    // ---- prologue: x regs for chunk 0; W chunk 0 via cp.async ----
    float4 xr[8];
#pragma unroll
    for (int j = 0; j < 4; j++) {
        const float* src = xbase + (size_t)(32 * j) * EMB;
        xr[2 * j]     = *(const float4*)(src);
        xr[2 * j + 1] = *(const float4*)(src + 4);
    }
    proj_w_prefetch(sb + PJ_W0, which, 0, tid);

    for (int c = 0; c < 16; c++) {
        const uint32_t wbuf = (c & 1) ? PJ_W1 : PJ_W0;

        // ---- 1. convert x regs -> smem X (X free: trailing barrier) ----
#pragma unroll
        for (int j = 0; j < 4; j++) {
            float4 u = xr[2 * j], v = xr[2 * j + 1];
            float s0 = totf32(u.x), s1 = totf32(u.y), s2 = totf32(u.z), s3 = totf32(u.w);
            float s4 = totf32(v.x), s5 = totf32(v.y), s6 = totf32(v.z), s7 = totf32(v.w);
            float* dst = (float*)(smem + PJ_X + (xrow0 + 32 * j) * PJ_RS + xc8 * 32);
            *(float4*)(dst)     = make_float4(s0, s4, s1, s5);
            *(float4*)(dst + 4) = make_float4(s2, s6, s3, s7);
        }

        // ---- 2. prefetch W[c+1] into other buffer; wait for W[c] ----
        if (c < 15) {
            proj_w_prefetch(sb + ((c & 1) ? PJ_W0 : PJ_W1), which, (c + 1) * 64, tid);
            CP_WAIT1();
        } else {
            CP_WAIT0();
        }
        __syncthreads();

        // ---- 3. prefetch x regs for chunk c+1 (completes under MMA) ----
        if (c < 15) {
            const float* xb1 = xbase + (c + 1) * 64;
#pragma unroll
            for (int j = 0; j < 4; j++) {
                const float* src = xb1 + (size_t)(32 * j) * EMB;
                xr[2 * j]     = *(const float4*)(src);
                xr[2 * j + 1] = *(const float4*)(src + 4);
            }
        }

        // ---- 4. MMA on X + W[c] ----
#pragma unroll
        for (int st = 0; st < 8; st++) {
            float2 aA0 = *(const float2*)(smem + PJ_X + a_row0 + st * 32);
            float2 aB0 = *(const float2*)(smem + PJ_X + a_row0 + 8 * PJ_RS + st * 32);
            float2 aA1 = *(const float2*)(smem + PJ_X + a_row0 + 16 * PJ_RS + st * 32);
            float2 aB1 = *(const float2*)(smem + PJ_X + a_row0 + 24 * PJ_RS + st * 32);
#pragma unroll
            for (int nt = 0; nt < 8; nt++) {
                float2 b = *(const float2*)(smem + wbuf + b_base
                                            + (uint32_t)(nt * 8) * PJ_RS + st * 32);
                mma_tf32(o[0][nt][0], o[0][nt][1], o[0][nt][2], o[0][nt][3],
                         aA0.x, aB0.x, aA0.y, aB0.y, b.x, b.y);
                mma_tf32(o[1][nt][0], o[1][nt][1], o[1][nt][2], o[1][nt][3],
                         aA1.x, aB1.x, aA1.y, aB1.y, b.x, b.y);
            }
        }

        __syncthreads();   // protect X (and retired W buf) before next overwrite
    }

    // ---- epilogue ----
#pragma unroll
    for (int mt = 0; mt < 2; mt++) {
        const int r0 = m0 + wm * 32 + mt * 16 + (lane >> 2);
        const int r1 = r0 + 8;
        if (which == 2) {
            // V: transpose into g_Vt[b][dim][seq], keys pair-permuted
            const int b0i = r0 >> 12, s0 = r0 & 4095;
            const int b1i = r1 >> 12, s1 = r1 & 4095;
            const int sp0 = (s0 & ~7) + perm8(s0 & 7);
            const int sp1 = (s1 & ~7) + perm8(s1 & 7);
#pragma unroll
            for (int nt = 0; nt < 8; nt++) {
                int col = wn * 64 + nt * 8 + 2 * (lane & 3);
                g_Vt[((size_t)b0i * HDIM + col)     * SEQ + sp0] = totf32(o[mt][nt][0]);
                g_Vt[((size_t)b0i * HDIM + col + 1) * SEQ + sp0] = totf32(o[mt][nt][1]);
                g_Vt[((size_t)b1i * HDIM + col)     * SEQ + sp1] = totf32(o[mt][nt][2]);
                g_Vt[((size_t)b1i * HDIM + col + 1) * SEQ + sp1] = totf32(o[mt][nt][3]);
            }
        } else {
            const float scale = (which == 1) ? (0.03125f * 1.44269504f) : 1.0f;
            float* dst = (which == 1) ? g_Q : g_K;
#pragma unroll
            for (int nt = 0; nt < 8; nt++) {
                int col = wn * 64 + nt * 8 + 2 * (lane & 3);
                int p0 = (col & ~7) + perm8(col & 7);
                int p1 = (col & ~7) + perm8((col & 7) + 1);
                dst[(size_t)r0 * HDIM + p0] = totf32(o[mt][nt][0] * scale);
                dst[(size_t)r0 * HDIM + p1] = totf32(o[mt][nt][1] * scale);
                dst[(size_t)r1 * HDIM + p0] = totf32(o[mt][nt][2] * scale);
                dst[(size_t)r1 * HDIM + p1] = totf32(o[mt][nt][3] * scale);
            }
        }
    }
}

// ===========================================================================
// Flash attention, tf32, 8 warps, FA2 key-split halves IN-CTA + 2-way
// key-parity split ACROSS CTAs (kt ≡ rho mod 2), partials to gmem.
// Pair trick: CTA handles q-tiles p and 63-p -> ~32.5 iters/CTA.
// grid (64, 4): p = bx>>1, rho = bx&1. 256 CTAs, 2 CTAs/SM (106496 B, <=128r).
// Q in smem (no reg hoist), K/V single-buffered (co-CTA hides load latency).
// ===========================================================================
#define AQ_RS  544
#define AK_RS  544
#define AV_RS  288
#define A_Q    0
#define A_K    34816
#define A_V    69632
#define A_SMEM 106496
#define M_INIT (-1e30f)

__global__ __launch_bounds__(256, 2) void attn_mma_kernel()
{
    char* smem = dsmem;
    uint32_t sb = smem_to_u32(smem);
    const int tid  = threadIdx.x;
    const int lane = tid & 31;
    const int w    = tid >> 5;
    const int wq   = w & 3;           // query-row group (16 rows)
    const int nh   = w >> 2;          // key half: 0 -> [0:32), 1 -> [32:64)
    const int b    = blockIdx.y;
    const int pair = blockIdx.x >> 1;
    const int rho  = blockIdx.x & 1;  // key-tile parity
    const int bbase = b * SEQ;

    const int r0 = wq * 16 + (lane >> 2);        // tile-local row (0..63)
    // P-shuffle lane map (C-frag -> A-frag)
    const int pc = lane & 3;
    const int src_lo = (lane & 28) | (pc >> 1);
    const int src_hi = src_lo | 2;
    const int pe = pc & 1;

    // fragment addressing (byte offsets within smem)
    const uint32_t qfo = (uint32_t)(wq * 16 + (lane >> 2)) * AQ_RS + (lane & 3) * 8;
    const uint32_t kfo = A_K + (uint32_t)(nh * 32 + (lane >> 2)) * AK_RS + (lane & 3) * 8;
    const uint32_t vfo = A_V + (uint32_t)(lane >> 2) * AV_RS + (nh * 32) * 4 + (lane & 3) * 8;

    for (int half = 0; half < 2; half++) {
        const int qt = half ? (63 - pair) : pair;

        // ---- stage Q tile into smem (already tf32 + pair-permuted) ----
        __syncthreads();
#pragma unroll
        for (int j = 0; j < 8; j++) {
            int idx = tid + j * 256;               // 0..2047
            int row = idx >> 5, c = idx & 31;
            *(uint4*)(smem + A_Q + (uint32_t)row * AQ_RS + c * 16) =
                *(const uint4*)(g_Q + (size_t)(bbase + qt * 64 + row) * HDIM + c * 4);
        }
        __syncthreads();

        float o[16][4];
#pragma unroll
        for (int t = 0; t < 16; t++)
#pragma unroll
            for (int k = 0; k < 4; k++) o[t][k] = 0.0f;
        float m0 = M_INIT, m1 = M_INIT, l0 = 0.0f, l1 = 0.0f;

        for (int kt = rho; kt <= qt; kt += 2) {
            const int grow = bbase + kt * 64;

            // ---- K and V^T loads (single buffer; trailing barrier freed it) ----
#pragma unroll
            for (int j = 0; j < 8; j++) {
                int idx = tid + j * 256;
                int row = idx >> 5, c = idx & 31;
                CP_ASYNC16(sb + A_K + (uint32_t)row * AK_RS + c * 16,
                           (const void*)(g_K + (size_t)(grow + row) * HDIM + c * 4));
            }
#pragma unroll
            for (int j = 0; j < 8; j++) {
                int idx = tid + j * 256;
                int row = idx >> 4, c = idx & 15;
                CP_ASYNC16(sb + A_V + (uint32_t)row * AV_RS + c * 16,
                           (const void*)(g_Vt + ((size_t)b * HDIM + row) * SEQ
                                         + kt * 64 + c * 4));
            }
            CP_COMMIT();
            CP_WAIT0();
            __syncthreads();

            // ---- S = Q K^T on this warp's 32-key half ----
            float s[4][4];
#pragma unroll
            for (int t = 0; t < 4; t++)
#pragma unroll
                for (int k = 0; k < 4; k++) s[t][k] = 0.0f;

#pragma unroll
            for (int st = 0; st < 16; st++) {
                float2 aA = *(const float2*)(smem + A_Q + qfo + st * 32);
                float2 aB = *(const float2*)(smem + A_Q + qfo + 8 * AQ_RS + st * 32);
#pragma unroll
                for (int np = 0; np < 4; np++) {
                    float2 bb = *(const float2*)(smem + kfo
                                 + (uint32_t)(np * 8) * AK_RS + st * 32);
                    mma_tf32(s[np][0], s[np][1], s[np][2], s[np][3],
                             aA.x, aB.x, aA.y, aB.y, bb.x, bb.y);
                }
            }

            // ---- causal mask on diagonal tile ----
            if (kt == qt) {
                const int rr0 = r0, rr1 = r0 + 8;
#pragma unroll
                for (int nt = 0; nt < 4; nt++) {
                    int c = nh * 32 + nt * 8 + 2 * (lane & 3);
                    if (c     > rr0) s[nt][0] = -INFINITY;
                    if (c + 1 > rr0) s[nt][1] = -INFINITY;
                    if (c     > rr1) s[nt][2] = -INFINITY;
                    if (c + 1 > rr1) s[nt][3] = -INFINITY;
                }
            }

            // ---- online softmax (base-2, independent per key-half) ----
            float rmax0 = -INFINITY, rmax1 = -INFINITY;
#pragma unroll
            for (int nt = 0; nt < 4; nt++) {
                rmax0 = fmaxf(rmax0, fmaxf(s[nt][0], s[nt][1]));
                rmax1 = fmaxf(rmax1, fmaxf(s[nt][2], s[nt][3]));
            }
            rmax0 = fmaxf(rmax0, __shfl_xor_sync(FULLM, rmax0, 1));
            rmax0 = fmaxf(rmax0, __shfl_xor_sync(FULLM, rmax0, 2));
            rmax1 = fmaxf(rmax1, __shfl_xor_sync(FULLM, rmax1, 1));
            rmax1 = fmaxf(rmax1, __shfl_xor_sync(FULLM, rmax1, 2));

            float mn0 = fmaxf(m0, rmax0), mn1 = fmaxf(m1, rmax1);
            float alpha0 = ex2(m0 - mn0), alpha1 = ex2(m1 - mn1);
            m0 = mn0; m1 = mn1;

            float sum0 = 0.0f, sum1 = 0.0f;
#pragma unroll
            for (int nt = 0; nt < 4; nt++) {
                s[nt][0] = ex2(s[nt][0] - mn0);
                s[nt][1] = ex2(s[nt][1] - mn0);
                s[nt][2] = ex2(s[nt][2] - mn1);
                s[nt][3] = ex2(s[nt][3] - mn1);
                sum0 += s[nt][0] + s[nt][1];
                sum1 += s[nt][2] + s[nt][3];
            }
            sum0 += __shfl_xor_sync(FULLM, sum0, 1);
            sum0 += __shfl_xor_sync(FULLM, sum0, 2);
            sum1 += __shfl_xor_sync(FULLM, sum1, 1);
            sum1 += __shfl_xor_sync(FULLM, sum1, 2);
            l0 = l0 * alpha0 + sum0;
            l1 = l1 * alpha1 + sum1;

#pragma unroll
            for (int t = 0; t < 16; t++) {
                o[t][0] *= alpha0; o[t][1] *= alpha0;
                o[t][2] *= alpha1; o[t][3] *= alpha1;
            }

            // ---- O += P V over this warp's 32-key range ----
#pragma unroll
            for (int t = 0; t < 4; t++) {
                float v0 = __shfl_sync(FULLM, s[t][0], src_lo);
                float v1 = __shfl_sync(FULLM, s[t][1], src_lo);
                float v2 = __shfl_sync(FULLM, s[t][2], src_lo);
                float v3 = __shfl_sync(FULLM, s[t][3], src_lo);
                float h0 = __shfl_sync(FULLM, s[t][0], src_hi);
                float h1 = __shfl_sync(FULLM, s[t][1], src_hi);
                float h2 = __shfl_sync(FULLM, s[t][2], src_hi);
                float h3 = __shfl_sync(FULLM, s[t][3], src_hi);
                float pa0 = totf32(pe ? v1 : v0);
                float pa1 = totf32(pe ? v3 : v2);
                float pa2 = totf32(pe ? h1 : h0);
                float pa3 = totf32(pe ? h3 : h2);
#pragma unroll
                for (int nd = 0; nd < 16; nd++) {
                    float2 bb = *(const float2*)(smem + vfo
                                 + (uint32_t)(nd * 8) * AV_RS + t * 32);
                    mma_tf32(o[nd][0], o[nd][1], o[nd][2], o[nd][3],
                             pa0, pa1, pa2, pa3, bb.x, bb.y);
                }
            }

            __syncthreads();   // all smem reads done -> buffer reusable
        }

        // ---- merge key-halves; write UNNORMALIZED partial for this parity ----
        float* O1s = (float*)(smem + A_K);          // [64][128] scratch
        float* M1s = (float*)(smem + A_K + 32768);  // [64]
        float* L1s = M1s + 64;                      // [64]
        if (nh == 1) {
#pragma unroll
            for (int nt = 0; nt < 16; nt++) {
                int col = nt * 8 + 2 * (lane & 3);
                *(float2*)(O1s + (r0)     * 128 + col) = make_float2(o[nt][0], o[nt][1]);
                *(float2*)(O1s + (r0 + 8) * 128 + col) = make_float2(o[nt][2], o[nt][3]);
            }
            if ((lane & 3) == 0) {
                M1s[r0] = m0;  M1s[r0 + 8] = m1;
                L1s[r0] = l0;  L1s[r0 + 8] = l1;
            }
        }
        __syncthreads();
        if (nh == 0) {
            float* Op = rho ? g_O1 : g_O0;
            float m1a = M1s[r0],     l1a = L1s[r0];
            float m1b = M1s[r0 + 8], l1b = L1s[r0 + 8];
            float Ma = fmaxf(m0, m1a), Mb = fmaxf(m1, m1b);
            float b0a = ex2(m0 - Ma),  b1a = ex2(m1a - Ma);
            float b0b = ex2(m1 - Mb),  b1b = ex2(m1b - Mb);
            float La = l0 * b0a + l1a * b1a;
            float Lb = l1 * b0b + l1b * b1b;
            const int gr0 = bbase + qt * 64 + r0;
            const int gr1 = gr0 + 8;
            if ((lane & 3) == 0) {
                g_Mp[rho][gr0] = Ma;  g_Lp[rho][gr0] = La;
                g_Mp[rho][gr1] = Mb;  g_Lp[rho][gr1] = Lb;
            }
#pragma unroll
            for (int nt = 0; nt < 16; nt++) {
                int col = nt * 8 + 2 * (lane & 3);
                float2 p0 = *(const float2*)(O1s + (r0)     * 128 + col);
                float2 p1 = *(const float2*)(O1s + (r0 + 8) * 128 + col);
                *(float2*)(Op + (size_t)gr0 * HDIM + col) = make_float2(
                    o[nt][0] * b0a + p0.x * b1a,
                    o[nt][1] * b0a + p0.y * b1a);
                *(float2*)(Op + (size_t)gr1 * HDIM + col) = make_float2(
                    o[nt][2] * b0b + p1.x * b1b,
                    o[nt][3] * b0b + p1.y * b1b);
            }
        }
    }
}

// ===========================================================================
// Merge the 2 parity partials, float4-vectorized:
// out = sum(O_p * 2^(m_p - M)) / sum(l_p * ...)
// ===========================================================================
__global__ __launch_bounds__(128) void attn_merge_kernel(float* __restrict__ out)
{
    int idx = blockIdx.x * 128 + threadIdx.x;    // one float4 per thread
    int row = idx >> 5;                          // 32 threads per row
    int col = (idx & 31) * 4;
    float m0 = g_Mp[0][row], m1 = g_Mp[1][row];
    float M  = fmaxf(m0, m1);
    float w0 = ex2(m0 - M), w1 = ex2(m1 - M);
    float invL = 1.0f / (g_Lp[0][row] * w0 + g_Lp[1][row] * w1);
    size_t off = (size_t)row * HDIM + col;
    float4 a = *(const float4*)(g_O0 + off);
    float4 bq = *(const float4*)(g_O1 + off);
    *(float4*)(out + off) = make_float4(
        (a.x * w0 + bq.x * w1) * invL,
        (a.y * w0 + bq.y * w1) * invL,
        (a.z * w0 + bq.z * w1) * invL,
        (a.w * w0 + bq.w * w1) * invL);
}

// ---------------------------------------------------------------------------
extern "C" void kernel_launch(void* const* d_in, const int* in_sizes, int n_in,
                              void* d_out, int out_size)
{
    const float* x  = (const float*)d_in[0];
    const float* Wk = (const float*)d_in[1];
    const float* Wq = (const float*)d_in[2];
    const float* Wv = (const float*)d_in[3];
    float* out = (float*)d_out;

    static bool attr_set = false;
    if (!attr_set) {
        cudaFuncSetAttribute(proj_mma_kernel,
                             cudaFuncAttributeMaxDynamicSharedMemorySize, PJ_SMEM);
        cudaFuncSetAttribute(attn_mma_kernel,
                             cudaFuncAttributeMaxDynamicSharedMemorySize, A_SMEM);
        attr_set = true;
    }

    // 1) prep W -> tf32-rounded, pair-permuted (x prep fused into proj)
    wprep_kernel<<<(3 * HDIM * EMB + 255) / 256, 256>>>(Wk, Wq, Wv);

    // 2) Q/K/V projections, tf32, software-pipelined (W cp.async + x reg prefetch)
    proj_mma_kernel<<<dim3(128, 3), 256, PJ_SMEM>>>(x);

    // 3) causal flash attention: 256 CTAs (pair x 2 key-parities), 2 CTAs/SM
    attn_mma_kernel<<<dim3(64, BATCH), 256, A_SMEM>>>();

    // 4) merge parity partials (float4 per thread)
    attn_merge_kernel<<<BATCH * SEQ * HDIM / 512, 128>>>(out);
}